// round 17
// baseline (speedup 1.0000x reference)
#include <cuda_runtime.h>
#include <cuda_bf16.h>
#include <cstdint>
#include <math.h>

#define NROW   100000
#define FD     128
#define BATCH  64
#define KP1    16385
#define NELEM  (BATCH*KP1)        // 1048640
#define NNEG   1048576.0          // 64*16384
#define INV_T  (1.0f/0.07f)
#define EPSC   1e-7
#define MPN    0.16384
#define NBX    9
#define NPART  (BATCH*NBX)        // 576
#define ESCALE 0.015625f          // 1/64 scaling for moment range
#define NKC    16                 // max embed split-k chunks (side1)

// ---- gemm smem layout (bf16 tiles, rows padded to 136 elems = 272B) ----
#define ROWB   272
#define OFF_AH 0
#define OFF_AL 34816
#define OFF_BH 69632
#define OFF_BL 87040
#define SMEM_DYN 104448

// ---------------- scratch (device globals; no allocation) ----------------
__device__ float g_yp[NKC][2*BATCH*FD];                    // embed split-k partials
__device__ __align__(16) __nv_bfloat16 g_Bh[2][BATCH*FD];  // v hi, [side][b*128+d]
__device__ __align__(16) __nv_bfloat16 g_Bl[2][BATCH*FD];  // v lo
__device__ float g_S[2][6400000];                          // [side][row*64+b]
__device__ float g_pM[NPART*8];                            // per-block moments m1..m4 x 2 sides

// =================== portable PTX helpers (sm_80+ features) ===================
__device__ __forceinline__ uint32_t smem_u32(const void* p) {
    uint32_t a;
    asm("{ .reg .u64 t; cvta.to.shared.u64 t, %1; cvt.u32.u64 %0, t; }" : "=r"(a) : "l"(p));
    return a;
}
__device__ __forceinline__ void ldmx4(uint32_t* r, uint32_t addr) {
    asm volatile("ldmatrix.sync.aligned.m8n8.x4.shared.b16 {%0,%1,%2,%3}, [%4];"
                 : "=r"(r[0]), "=r"(r[1]), "=r"(r[2]), "=r"(r[3]) : "r"(addr));
}
__device__ __forceinline__ void mma16816(float* d, const uint32_t* a,
                                         uint32_t b0, uint32_t b1) {
    asm volatile(
        "mma.sync.aligned.m16n8k16.row.col.f32.bf16.bf16.f32 "
        "{%0,%1,%2,%3}, {%4,%5,%6,%7}, {%8,%9}, {%0,%1,%2,%3};"
        : "+f"(d[0]), "+f"(d[1]), "+f"(d[2]), "+f"(d[3])
        : "r"(a[0]), "r"(a[1]), "r"(a[2]), "r"(a[3]), "r"(b0), "r"(b1));
}

// ---------------- embed GEMM, side-asymmetric split-k, float4 smem ----------------
// grid x: [0,32) -> side0 (8 kc x 4 ft), [32,96) -> side1 (16 kc x 4 ft). klen=128 both.
__global__ void embed_kernel(const float* __restrict__ f_s, const float* __restrict__ f_t,
                             const float* __restrict__ Ws,  const float* __restrict__ Wt) {
    int x = blockIdx.x;
    int side = (x >= 32) ? 1 : 0;
    int loc  = side ? (x - 32) : x;
    int ft = loc & 3;
    int kc = loc >> 2;
    const float* f = side ? f_t : f_s;
    const float* W = side ? Wt  : Ws;
    int dim  = side ? 2048 : 1024;
    int kbeg = kc * 128;

    __shared__ float Fs[64][68];
    __shared__ float Wc[32][68];

    int tid = threadIdx.x;
    int tx  = tid & 31;
    int bg  = tid >> 5;
    int ftb = ft * 32;

    const float4* f4 = reinterpret_cast<const float4*>(f);
    const float4* W4 = reinterpret_cast<const float4*>(W);
    int dim4 = dim >> 2;

    float acc[8] = {0.f,0.f,0.f,0.f,0.f,0.f,0.f,0.f};

    #pragma unroll
    for (int k0 = kbeg; k0 < kbeg + 128; k0 += 64) {
        // stage f tile: 64 rows x 16 float4
        #pragma unroll
        for (int j = 0; j < 4; j++) {
            int lin = tid + j*256;
            int r = lin >> 4, c = lin & 15;
            *reinterpret_cast<float4*>(&Fs[r][c*4]) = f4[r*dim4 + (k0 >> 2) + c];
        }
        // stage W tile: 32 rows x 16 float4
        #pragma unroll
        for (int j = 0; j < 2; j++) {
            int lin = tid + j*256;
            int r = lin >> 4, c = lin & 15;
            *reinterpret_cast<float4*>(&Wc[r][c*4]) = W4[(ftb + r)*dim4 + (k0 >> 2) + c];
        }
        __syncthreads();
        #pragma unroll
        for (int k4 = 0; k4 < 16; k4++) {
            float4 wv = *reinterpret_cast<const float4*>(&Wc[tx][k4*4]);
            #pragma unroll
            for (int j = 0; j < 8; j++) {
                float4 fv = *reinterpret_cast<const float4*>(&Fs[bg*8 + j][k4*4]);
                acc[j] += wv.x*fv.x + wv.y*fv.y + wv.z*fv.z + wv.w*fv.w;
            }
        }
        __syncthreads();
    }
    #pragma unroll
    for (int j = 0; j < 8; j++)
        g_yp[kc][side*BATCH*FD + (bg*8 + j)*FD + ftb + tx] = acc[j];
}

// ---------------- norm: sum partials + bias + l2norm + bf16 hi/lo B ----------------
__global__ void norm_kernel(const float* __restrict__ bs, const float* __restrict__ bt) {
    int side = blockIdx.y, b = blockIdx.x, d = threadIdx.x;
    const float* bias = side ? bt : bs;
    int o = side*BATCH*FD + b*FD + d;
    int nkc = side ? 16 : 8;
    float y = bias[d];
    for (int kc = 0; kc < nkc; kc++) y += g_yp[kc][o];
    float s = y * y;
    #pragma unroll
    for (int of = 16; of > 0; of >>= 1) s += __shfl_xor_sync(0xffffffffu, s, of);
    __shared__ float sh[4];
    if ((d & 31) == 0) sh[d >> 5] = s;
    __syncthreads();
    float inv = rsqrtf(sh[0] + sh[1] + sh[2] + sh[3]);
    float v = y * inv;

    __nv_bfloat16 hi = __float2bfloat16_rn(v);
    __nv_bfloat16 lo = __float2bfloat16_rn(v - __bfloat162float(hi));
    g_Bh[side][b*FD + d] = hi;
    g_Bl[side][b*FD + d] = lo;
}

// ---------------- tensor GEMM, K-split pipelined, fused fragments ----------------
__global__ void __launch_bounds__(256, 2)
gemm_mma(const float* __restrict__ mem1, const float* __restrict__ mem2) {
    int side = blockIdx.y;
    const float* A = side ? mem1 : mem2;
    int r0 = blockIdx.x * 128;

    extern __shared__ __align__(16) unsigned char sm[];
    uint32_t base_u = smem_u32(sm);

    int tid  = threadIdx.x;
    int lane = tid & 31;
    int warp = tid >> 5;

    // ---- B tiles: copy pre-split hi/lo [64][128] into padded smem ----
    {
        const uint2* shp = reinterpret_cast<const uint2*>(&g_Bh[side][0]);
        const uint2* slp = reinterpret_cast<const uint2*>(&g_Bl[side][0]);
        #pragma unroll
        for (int i = 0; i < 8; i++) {
            int idx = tid + i*256;
            int r = idx >> 5, c = idx & 31;
            *reinterpret_cast<uint2*>(sm + OFF_BH + r*ROWB + c*8) = shp[idx];
            *reinterpret_cast<uint2*>(sm + OFF_BL + r*ROWB + c*8) = slp[idx];
        }
    }

    const float4* gA = reinterpret_cast<const float4*>(A);

    // ---- A half0 (K cols 0..63): load, split, STS ----
    #pragma unroll
    for (int i = 0; i < 8; i++) {
        int lin = tid + i*256;
        int r = lin >> 4, d4 = lin & 15;
        int gr = r0 + r; if (gr >= NROW) gr = NROW - 1;
        float4 a = gA[(size_t)gr*32 + d4];
        __nv_bfloat162 h01 = __floats2bfloat162_rn(a.x, a.y);
        __nv_bfloat162 h23 = __floats2bfloat162_rn(a.z, a.w);
        __nv_bfloat162 q01 = __floats2bfloat162_rn(a.x - __bfloat162float(h01.x),
                                                   a.y - __bfloat162float(h01.y));
        __nv_bfloat162 q23 = __floats2bfloat162_rn(a.z - __bfloat162float(h23.x),
                                                   a.w - __bfloat162float(h23.y));
        uint32_t doff = r*ROWB + d4*8;
        *reinterpret_cast<uint2*>(sm + OFF_AH + doff) =
            make_uint2(*reinterpret_cast<uint32_t*>(&h01), *reinterpret_cast<uint32_t*>(&h23));
        *reinterpret_cast<uint2*>(sm + OFF_AL + doff) =
            make_uint2(*reinterpret_cast<uint32_t*>(&q01), *reinterpret_cast<uint32_t*>(&q23));
    }

    // ---- issue A half1 loads BEFORE the barrier ----
    float4 a1[8];
    #pragma unroll
    for (int i = 0; i < 8; i++) {
        int lin = tid + i*256;
        int r = lin >> 4, d4 = lin & 15;
        int gr = r0 + r; if (gr >= NROW) gr = NROW - 1;
        a1[i] = gA[(size_t)gr*32 + 16 + d4];
    }
    __syncthreads();

    // ---- fragment setup: warp tile 32(m) x 32(n) ----
    int wm = (warp & 3) * 32;
    int wn = (warp >> 2) * 32;
    uint32_t aoff = (uint32_t)(wm + (lane & 15)) * ROWB + ((lane >> 4) * 8) * 2;
    uint32_t boff = (uint32_t)(wn + (lane & 7) + ((lane >> 4) << 3)) * ROWB
                  + (((lane >> 3) & 1) * 8) * 2;

    float dacc[2][4][4];
    #pragma unroll
    for (int mb = 0; mb < 2; mb++)
        #pragma unroll
        for (int nb = 0; nb < 4; nb++)
            #pragma unroll
            for (int e = 0; e < 4; e++) dacc[mb][nb][e] = 0.f;

#define COMPUTE_HALF(KB)                                                      \
    _Pragma("unroll")                                                         \
    for (int ks = (KB); ks < (KB) + 4; ks++) {                                \
        uint32_t ahk = base_u + OFF_AH + aoff + ks*32;                        \
        uint32_t alk = base_u + OFF_AL + aoff + ks*32;                        \
        uint32_t bhk = base_u + OFF_BH + boff + ks*32;                        \
        uint32_t blk = base_u + OFF_BL + boff + ks*32;                        \
        uint32_t ah0[4], ah1[4], al0[4], al1[4];                              \
        uint32_t bh0[4], bh1[4], bl0[4], bl1[4];                              \
        ldmx4(ah0, ahk);                                                      \
        ldmx4(ah1, ahk + 16*ROWB);                                            \
        ldmx4(bh0, bhk);                                                      \
        ldmx4(bh1, bhk + 16*ROWB);                                            \
        ldmx4(al0, alk);                                                      \
        ldmx4(al1, alk + 16*ROWB);                                            \
        ldmx4(bl0, blk);                                                      \
        ldmx4(bl1, blk + 16*ROWB);                                            \
        mma16816(dacc[0][0], ah0, bh0[0], bh0[1]);                            \
        mma16816(dacc[0][1], ah0, bh0[2], bh0[3]);                            \
        mma16816(dacc[0][2], ah0, bh1[0], bh1[1]);                            \
        mma16816(dacc[0][3], ah0, bh1[2], bh1[3]);                            \
        mma16816(dacc[1][0], ah1, bh0[0], bh0[1]);                            \
        mma16816(dacc[1][1], ah1, bh0[2], bh0[3]);                            \
        mma16816(dacc[1][2], ah1, bh1[0], bh1[1]);                            \
        mma16816(dacc[1][3], ah1, bh1[2], bh1[3]);                            \
        mma16816(dacc[0][0], ah0, bl0[0], bl0[1]);                            \
        mma16816(dacc[0][1], ah0, bl0[2], bl0[3]);                            \
        mma16816(dacc[0][2], ah0, bl1[0], bl1[1]);                            \
        mma16816(dacc[0][3], ah0, bl1[2], bl1[3]);                            \
        mma16816(dacc[1][0], ah1, bl0[0], bl0[1]);                            \
        mma16816(dacc[1][1], ah1, bl0[2], bl0[3]);                            \
        mma16816(dacc[1][2], ah1, bl1[0], bl1[1]);                            \
        mma16816(dacc[1][3], ah1, bl1[2], bl1[3]);                            \
        mma16816(dacc[0][0], al0, bh0[0], bh0[1]);                            \
        mma16816(dacc[0][1], al0, bh0[2], bh0[3]);                            \
        mma16816(dacc[0][2], al0, bh1[0], bh1[1]);                            \
        mma16816(dacc[0][3], al0, bh1[2], bh1[3]);                            \
        mma16816(dacc[1][0], al1, bh0[0], bh0[1]);                            \
        mma16816(dacc[1][1], al1, bh0[2], bh0[3]);                            \
        mma16816(dacc[1][2], al1, bh1[0], bh1[1]);                            \
        mma16816(dacc[1][3], al1, bh1[2], bh1[3]);                            \
    }

    COMPUTE_HALF(0)

    // ---- split + STS half1 (disjoint bytes vs half0 readers) ----
    #pragma unroll
    for (int i = 0; i < 8; i++) {
        int lin = tid + i*256;
        int r = lin >> 4, d4 = lin & 15;
        float4 a = a1[i];
        __nv_bfloat162 h01 = __floats2bfloat162_rn(a.x, a.y);
        __nv_bfloat162 h23 = __floats2bfloat162_rn(a.z, a.w);
        __nv_bfloat162 q01 = __floats2bfloat162_rn(a.x - __bfloat162float(h01.x),
                                                   a.y - __bfloat162float(h01.y));
        __nv_bfloat162 q23 = __floats2bfloat162_rn(a.z - __bfloat162float(h23.x),
                                                   a.w - __bfloat162float(h23.y));
        uint32_t doff = r*ROWB + 128 + d4*8;
        *reinterpret_cast<uint2*>(sm + OFF_AH + doff) =
            make_uint2(*reinterpret_cast<uint32_t*>(&h01), *reinterpret_cast<uint32_t*>(&h23));
        *reinterpret_cast<uint2*>(sm + OFF_AL + doff) =
            make_uint2(*reinterpret_cast<uint32_t*>(&q01), *reinterpret_cast<uint32_t*>(&q23));
    }
    __syncthreads();

    COMPUTE_HALF(4)
#undef COMPUTE_HALF

    // ---- epilogue: direct fragment -> STG.64 ----
    float* Sout = g_S[side];
    #pragma unroll
    for (int mb = 0; mb < 2; mb++) {
        #pragma unroll
        for (int nb = 0; nb < 4; nb++) {
            int row = r0 + wm + mb*16 + (lane >> 2);
            int col = wn + nb*8 + (lane & 3)*2;
            if (row < NROW)
                *reinterpret_cast<float2*>(&Sout[(size_t)row*64 + col]) =
                    make_float2(dacc[mb][nb][0], dacc[mb][nb][1]);
            if (row + 8 < NROW)
                *reinterpret_cast<float2*>(&Sout[(size_t)(row+8)*64 + col]) =
                    make_float2(dacc[mb][nb][2], dacc[mb][nb][3]);
        }
    }
}

// ---------------- moments: gather + exp + raw moments m1..m4 per side ----------------
// 8 elems/thread, staged (indices -> 16 in-flight LDGs -> math) for MLP
__global__ void moments_kernel(const int* __restrict__ idx, const int* __restrict__ cidx) {
    int b = blockIdx.y, bx = blockIdx.x;
    int t = threadIdx.x;
    int lane = t & 31, warp = t >> 5;
    const float* S0 = g_S[0];
    const float* S1 = g_S[1];

    int rows[8];
    #pragma unroll
    for (int i = 0; i < 8; i++) {
        int k = bx*2048 + i*256 + t;
        rows[i] = (k < KP1) ? ((k == 0) ? idx[b] : cidx[b*KP1 + k]) : -1;
    }
    float s0v[8], s1v[8];
    #pragma unroll
    for (int i = 0; i < 8; i++) {
        if (rows[i] >= 0) {
            size_t off = (size_t)rows[i]*64 + b;
            s0v[i] = S0[off];
            s1v[i] = S1[off];
        }
    }
    float m[8] = {0.f,0.f,0.f,0.f,0.f,0.f,0.f,0.f};
    #pragma unroll
    for (int i = 0; i < 8; i++) {
        if (rows[i] >= 0) {
            float e0 = __expf(s0v[i] * INV_T) * ESCALE;
            float e1 = __expf(s1v[i] * INV_T) * ESCALE;
            float p;
            m[0] += e0; p = e0*e0; m[1] += p; m[2] += p*e0; m[3] += p*p;
            m[4] += e1; p = e1*e1; m[5] += p; m[6] += p*e1; m[7] += p*p;
        }
    }
    #pragma unroll
    for (int j = 0; j < 8; j++)
        #pragma unroll
        for (int o = 16; o > 0; o >>= 1)
            m[j] += __shfl_xor_sync(0xffffffffu, m[j], o);
    __shared__ float sw[8][9];
    if (lane == 0)
        #pragma unroll
        for (int j = 0; j < 8; j++) sw[warp][j] = m[j];
    __syncthreads();
    if (t < 8) {
        float s = 0.f;
        #pragma unroll
        for (int w = 0; w < 8; w++) s += sw[w][t];
        g_pM[(b*NBX + bx)*8 + t] = s;
    }
}

// ---------------- final: warp-parallel moment reduce + positives ----------------
__global__ void final_kernel(const int* __restrict__ idx, float* __restrict__ out) {
    int t = threadIdx.x, lane = t & 31, w = t >> 5;
    __shared__ double dmom[8];
    __shared__ double spos[2][5][64];

    double s = 0.0;
    for (int i = lane; i < NPART; i += 32) s += (double)g_pM[i*8 + w];
    #pragma unroll
    for (int o = 16; o > 0; o >>= 1) s += __shfl_xor_sync(0xffffffffu, s, o);
    if (lane == 0) dmom[w] = s;
    __syncthreads();

    if (t < 128) {
        int side = t >> 6, b = t & 63;
        int row = idx[b];
        float s0 = g_S[side][(size_t)row*64 + b];
        float e0 = __expf(s0 * INV_T);
        float es = e0 * ESCALE, p2 = es*es;
        spos[side][0][b] = (double)es;
        spos[side][1][b] = (double)p2;
        spos[side][2][b] = (double)(p2*es);
        spos[side][3][b] = (double)(p2*p2);
        double E = 64.0 * dmom[side*4 + 0];
        double Z = E * (double)NROW / (double)NELEM;
        spos[side][4][b] = log1p((MPN + EPSC) * Z / (double)e0);
    }
    __syncthreads();

    if (t == 0) {
        const double cu    = (double)NELEM / ((double)NROW * MPN);
        const double delta = EPSC / MPN;
        double total = 0.0;
        for (int s2 = 0; s2 < 2; s2++) {
            double dp[5];
            #pragma unroll
            for (int j = 0; j < 5; j++) {
                double a = 0.0;
                for (int b2 = 0; b2 < 64; b2++) a += spos[s2][j][b2];
                dp[j] = a;
            }
            double M1 = dmom[s2*4 + 0];
            double E  = 64.0 * M1;
            double N1 = M1           - dp[0];
            double N2 = dmom[s2*4+1] - dp[1];
            double N3 = dmom[s2*4+2] - dp[2];
            double N4 = dmom[s2*4+3] - dp[3];
            double r  = 64.0 * cu / E;
            double S1 = r*N1, S2 = r*r*N2, S3 = r*r*r*N3, S4 = r*r*r*r*N4;
            double n  = NNEG;
            double P1 = S1 + n*delta;
            double P2 = S2 + 2.0*delta*S1 + n*delta*delta;
            double P3 = S3 + 3.0*delta*S2 + 3.0*delta*delta*S1;
            double P4 = S4 + 4.0*delta*S3 + 6.0*delta*delta*S2;
            double lneg = P1 - 0.5*P2 + P3/3.0 - 0.25*P4;
            total += lneg + dp[4];
        }
        out[0] = (float)(total / (double)BATCH);
    }
}

// ---------------- launch ----------------
extern "C" void kernel_launch(void* const* d_in, const int* in_sizes, int n_in,
                              void* d_out, int out_size) {
    const float* f_s  = (const float*)d_in[0];
    const float* f_t  = (const float*)d_in[1];
    const int*   idx  = (const int*)  d_in[2];
    const int*   cidx = (const int*)  d_in[3];
    const float* Ws   = (const float*)d_in[4];
    const float* bs   = (const float*)d_in[5];
    const float* Wt   = (const float*)d_in[6];
    const float* bt   = (const float*)d_in[7];
    const float* mem1 = (const float*)d_in[8];
    const float* mem2 = (const float*)d_in[9];

    cudaFuncSetAttribute(gemm_mma, cudaFuncAttributeMaxDynamicSharedMemorySize, SMEM_DYN);

    embed_kernel  <<<96,               256>>>(f_s, f_t, Ws, Wt);
    norm_kernel   <<<dim3(BATCH, 2),   128>>>(bs, bt);
    gemm_mma      <<<dim3(782, 2),     256, SMEM_DYN>>>(mem1, mem2);
    moments_kernel<<<dim3(NBX, BATCH), 256>>>(idx, cidx);
    final_kernel  <<<1,                256>>>(idx, (float*)d_out);
}